// round 6
// baseline (speedup 1.0000x reference)
#include <cuda_runtime.h>
#include <stdint.h>

// DynamicPatching: B=32, C=64, T=8192, S=64.
// out[b][s][c][p] = (p < len_bs) ? tensor[b][c][start_bs + p] : 0
// Output (B, S, C, max_len) row-major.
//
// Flat-region formulation: each block owns 32 consecutive output rows =
// one contiguous span of 32*max_len floats. One alignment fixup per block,
// STG.128 everywhere, (c,p) recovered per chunk by exact magic division.
// Pad chunks are store-only (no loads, no predicates).

#define PB 32
#define PC 64
#define PT 8192
#define PS 64

__device__ __forceinline__ float ldcs(const float* p) {
    float v;
    asm volatile("ld.global.cs.f32 %0, [%1];" : "=f"(v) : "l"(p));
    return v;
}
__device__ __forceinline__ void stcs4(float* p, float4 v) {
    asm volatile("st.global.cs.v4.f32 [%0], {%1,%2,%3,%4};"
                 :: "l"(p), "f"(v.x), "f"(v.y), "f"(v.z), "f"(v.w) : "memory");
}

__global__ void __launch_bounds__(256)
dynamic_patching_kernel(const float* __restrict__ tensor,
                        const int*   __restrict__ cps,   // (B, S+1) int32
                        float*       __restrict__ out,
                        int max_len,
                        unsigned magic)                  // ceil(2^32 / max_len)
{
    // One block per (b, s, half): 32 channels, contiguous output span.
    const int bs   = blockIdx.x >> 1;
    const int half = blockIdx.x & 1;
    const int b    = bs >> 6;            // / PS
    const int s    = bs & (PS - 1);      // % PS

    const int start = __ldg(cps + b * (PS + 1) + s);
    const int len   = __ldg(cps + b * (PS + 1) + s + 1) - start;

    // Source base: channel c_local in [0,32) -> srcB + c_local*PT + p.
    const float* __restrict__ srcB =
        tensor + ((size_t)b * PC + half * 32) * PT + start;

    // Output span: [gbase, gbase + 32*max_len) floats, contiguous.
    const long long gbase =
        ((long long)bs * PC + half * 32) * (long long)max_len;
    float* __restrict__ dstR = out + gbase;

    const int n  = max_len << 5;                    // 32 * max_len
    const int h  = (int)((4 - (gbase & 3)) & 3);    // head elems before 16B align
    const int nv = (n - h) >> 2;                    // # float4 chunks
    const int ts = h + (nv << 2);                   // tail start

    const unsigned tid = threadIdx.x;

    // Head (< 4 elems) and tail (< 4 elems), elementwise.
    if (tid < (unsigned)h) {
        const int li = (int)tid;                    // li < 4 -> c = 0, p = li
        dstR[li] = (li < len) ? ldcs(srcB + li) : 0.0f;
    }
    if (tid < (unsigned)(n - ts)) {
        const int li = ts + (int)tid;
        const int ci = (int)__umulhi((unsigned)li, magic);
        const int pi = li - ci * max_len;
        dstR[li] = (pi < len) ? ldcs(srcB + (size_t)ci * PT + pi) : 0.0f;
    }

    // Vector body: chunk k -> flat local offset h + 4k.
    #pragma unroll 2
    for (int k = (int)tid; k < nv; k += 256) {
        const int local = h + (k << 2);
        const int c = (int)__umulhi((unsigned)local, magic);
        const int p = local - c * max_len;
        float4 v;

        if (p + 4 <= max_len) {                     // chunk inside one row
            if (p + 4 <= len) {                     // fully valid: no predicates
                const float* sp = srcB + (size_t)c * PT + p;
                v.x = ldcs(sp + 0);
                v.y = ldcs(sp + 1);
                v.z = ldcs(sp + 2);
                v.w = ldcs(sp + 3);
            } else if (p >= len) {                  // fully padded: store-only
                v = make_float4(0.0f, 0.0f, 0.0f, 0.0f);
            } else {                                // valid/pad boundary (~1/row)
                const float* sp = srcB + (size_t)c * PT + p;
                v.x = (p + 0 < len) ? ldcs(sp + 0) : 0.0f;
                v.y = (p + 1 < len) ? ldcs(sp + 1) : 0.0f;
                v.z = (p + 2 < len) ? ldcs(sp + 2) : 0.0f;
                v.w = (p + 3 < len) ? ldcs(sp + 3) : 0.0f;
            }
        } else {                                    // straddles a row boundary
            float t[4];
            #pragma unroll
            for (int i = 0; i < 4; ++i) {
                const int li = local + i;
                const int ci = (int)__umulhi((unsigned)li, magic);
                const int pi = li - ci * max_len;
                t[i] = (pi < len) ? ldcs(srcB + (size_t)ci * PT + pi) : 0.0f;
            }
            v = make_float4(t[0], t[1], t[2], t[3]);
        }

        stcs4(dstR + local, v);                     // dst always contiguous
    }
}

extern "C" void kernel_launch(void* const* d_in, const int* in_sizes, int n_in,
                              void* d_out, int out_size)
{
    const float* tensor = (const float*)d_in[0];
    const int*   cps    = (const int*)d_in[1];
    float*       out    = (float*)d_out;

    const int max_len = out_size / (PB * PS * PC);
    // Exact unsigned division by max_len for dividends < ~2^20:
    // magic = ceil(2^32 / max_len); c = umulhi(x, magic).
    const unsigned magic =
        (unsigned)((0x100000000ULL + (unsigned)max_len - 1) / (unsigned)max_len);

    dynamic_patching_kernel<<<PB * PS * 2, 256>>>(tensor, cps, out, max_len, magic);
}

// round 7
// speedup vs baseline: 1.0893x; 1.0893x over previous
#include <cuda_runtime.h>

// DynamicPatching: B=32, C=64, T=8192, S=64.
// out[b][s][c][p] = (p < len_bs) ? tensor[b][c][start_bs + p] : 0
// Output (B, S, C, max_len) row-major.
//
// R4 structure (two-phase: 16 batched predicated loads across 4 rows, then
// 4 STG.128) with register diet: no pointer arrays — two base pointers, row
// offsets folded into address IMADs. __launch_bounds__(256,8) pins regs<=32
// so occupancy recovers to ~8 blocks/SM while keeping MLP ~16.

#define PB 32
#define PC 64
#define PT 8192
#define PS 64

__device__ __forceinline__ float ldcs(const float* p) {
    float v;
    asm volatile("ld.global.cs.f32 %0, [%1];" : "=f"(v) : "l"(p));
    return v;
}
__device__ __forceinline__ void stcs4(float* p, float4 v) {
    asm volatile("st.global.cs.v4.f32 [%0], {%1,%2,%3,%4};"
                 :: "l"(p), "f"(v.x), "f"(v.y), "f"(v.z), "f"(v.w) : "memory");
}

__global__ void __launch_bounds__(256, 8)
dynamic_patching_kernel(const float* __restrict__ tensor,
                        const int*   __restrict__ cps,   // (B, S+1) int32
                        float*       __restrict__ out,
                        int max_len)
{
    // 2 blocks per (b,s): each block covers 32 of the 64 channels.
    const int bs   = blockIdx.x >> 1;
    const int half = blockIdx.x & 1;
    const int b    = bs >> 6;            // / PS
    const int s    = bs & (PS - 1);      // % PS

    const int start = __ldg(cps + b * (PS + 1) + s);
    const int len   = __ldg(cps + b * (PS + 1) + s + 1) - start;

    const int wid  = threadIdx.x >> 5;   // 0..7
    const int lane = threadIdx.x & 31;
    const int c0   = half * 32 + wid * 4;          // warp's first channel

    // Warp base pointers; row r adds r*PT (src) / r*max_len (dst).
    const float* __restrict__ srcB =
        tensor + ((size_t)b * PC + c0) * PT + start;
    const long long dbase =
        ((long long)bs * PC + c0) * (long long)max_len;
    float* __restrict__ dstB = out + dbase;

    // Per-row alignment: p0[r] = first 16B-aligned offset in row r.
    int p0[4], nv[4];
    int nvmax = 0;
    #pragma unroll
    for (int r = 0; r < 4; ++r) {
        p0[r] = (int)((4 - ((dbase + (long long)r * max_len) & 3)) & 3);
        nv[r] = (max_len - p0[r]) >> 2;
        nvmax = max(nvmax, nv[r]);
    }

    // Heads (< p0) and tails (< 4 elems), hoisted out of the hot loop.
    #pragma unroll
    for (int r = 0; r < 4; ++r) {
        if (lane < p0[r])
            dstB[(long long)r * max_len + lane] =
                (lane < len) ? ldcs(srcB + r * PT + lane) : 0.0f;
        const int p = p0[r] + (nv[r] << 2) + lane;
        if (p < max_len)
            dstB[(long long)r * max_len + p] =
                (p < len) ? ldcs(srcB + r * PT + p) : 0.0f;
    }

    // Hot loop: phase 1 issues 16 independent predicated loads (4 rows x 4),
    // phase 2 issues 4 STG.128. Addresses derived from bases each iteration.
    for (int kb = 0; kb < nvmax; kb += 32) {
        const int k = kb + lane;
        float4 v[4];

        #pragma unroll
        for (int r = 0; r < 4; ++r) {
            const int p = p0[r] + (k << 2);
            v[r] = make_float4(0.0f, 0.0f, 0.0f, 0.0f);
            if (k < nv[r]) {
                const float* sp = srcB + r * PT + p;
                if (p + 0 < len) v[r].x = ldcs(sp + 0);
                if (p + 1 < len) v[r].y = ldcs(sp + 1);
                if (p + 2 < len) v[r].z = ldcs(sp + 2);
                if (p + 3 < len) v[r].w = ldcs(sp + 3);
            }
        }

        #pragma unroll
        for (int r = 0; r < 4; ++r) {
            if (k < nv[r])
                stcs4(dstB + (long long)r * max_len + p0[r] + (k << 2), v[r]);
        }
    }
}

extern "C" void kernel_launch(void* const* d_in, const int* in_sizes, int n_in,
                              void* d_out, int out_size)
{
    const float* tensor = (const float*)d_in[0];
    const int*   cps    = (const int*)d_in[1];
    float*       out    = (float*)d_out;

    const int max_len = out_size / (PB * PS * PC);

    dynamic_patching_kernel<<<PB * PS * 2, 256>>>(tensor, cps, out, max_len);
}